// round 2
// baseline (speedup 1.0000x reference)
#include <cuda_runtime.h>
#include <math.h>

#define BB 4
#define TQ 2048
#define TT 2048
#define EE 2048
#define HH 16
#define DD 128
#define HD (HH*DD)
#define NBLOCK 4096

// -------- scratch (no allocations allowed; __device__ globals) --------
__device__ float g_q[(size_t)BB*HH*TQ*DD];     // [B,H,TQ,D]
__device__ float g_k[(size_t)BB*HH*TT*DD];     // [B,H,T,D]
__device__ float g_v[(size_t)BB*HH*TT*DD];     // [B,H,T,D]
__device__ float g_y[(size_t)BB*TQ*HD];        // [B,TQ,H*D]
__device__ float g_cos[(size_t)NBLOCK*DD];
__device__ float g_sin[(size_t)NBLOCK*DD];
__device__ unsigned char g_mask_u8[(size_t)BB*TT];
__device__ int g_mask_mode;

// -------- mask dtype detection (bool may arrive as u8 / i32 / f32) ---------
__global__ void mask_detect_kernel(const unsigned int* __restrict__ m) {
    __shared__ int s_not01, s_notf;
    if (threadIdx.x == 0) { s_not01 = 0; s_notf = 0; }
    __syncthreads();
    int not01 = 0, notf = 0;
    // first 2048 words = 8KB, in-bounds under every dtype interpretation
    for (int i = threadIdx.x; i < 2048; i += 256) {
        unsigned int w = m[i];
        if (w != 0u && w != 1u) not01 = 1;
        if (w != 0u && w != 0x3F800000u) notf = 1;
    }
    if (not01) atomicOr(&s_not01, 1);
    if (notf) atomicOr(&s_notf, 1);
    __syncthreads();
    if (threadIdx.x == 0) {
        int mode;
        if (!s_not01) mode = 1;        // int32 values 0/1
        else if (!s_notf) mode = 2;    // float32 values 0.0/1.0
        else mode = 0;                 // packed uint8
        g_mask_mode = mode;
    }
}

__global__ void mask_convert_kernel(const void* __restrict__ m) {
    int i = blockIdx.x * 256 + threadIdx.x;   // BB*TT = 8192 total
    int mode = g_mask_mode;
    unsigned char v;
    if (mode == 1)      v = (((const int*)m)[i] != 0);
    else if (mode == 2) v = (((const float*)m)[i] != 0.0f);
    else                v = (((const unsigned char*)m)[i] != 0);
    g_mask_u8[i] = v;
}

// -------- RoPE tables: double pow for inv_freq, fp32 multiply like jax -----
__global__ void rope_tables_kernel() {
    int p = blockIdx.x;          // position 0..4095
    int d = threadIdx.x;         // 0..127
    int j = d & 63;
    double inv = pow(10000.0, -((double)(2 * j)) / 128.0);
    float f = (float)p * (float)inv;
    g_cos[(size_t)p * DD + d] = cosf(f);
    g_sin[(size_t)p * DD + d] = sinf(f);
}

// -------- SGEMM: C[M,N] = A[M,K] @ W[K,N], fp32, 128x128x8 tile ------------
// MODE 0: plain row-major store. MODE 1: store to [B,H,T,D] (m=b*T+t, n=h*D+d)
template <int MODE>
__global__ __launch_bounds__(256, 2)
void sgemm_kernel(const float* __restrict__ A, const float* __restrict__ W,
                  float* __restrict__ C, int M, int N, int K) {
    __shared__ __align__(16) float As[8][128];
    __shared__ __align__(16) float Bs[8][128];

    const int tid = threadIdx.x;
    const int m0 = blockIdx.y * 128;
    const int n0 = blockIdx.x * 128;

    const int ar = tid >> 1, ac = (tid & 1) * 4;      // A tile loader
    const int br = tid >> 5, bc = (tid & 31) * 4;     // B tile loader
    const float* Aptr = A + (size_t)(m0 + ar) * K + ac;
    const float* Bptr = W + (size_t)br * N + n0 + bc;

    const int tx = tid & 15, ty = tid >> 4;

    float acc[8][8];
#pragma unroll
    for (int i = 0; i < 8; i++)
#pragma unroll
        for (int j = 0; j < 8; j++) acc[i][j] = 0.0f;

    for (int k0 = 0; k0 < K; k0 += 8) {
        float4 av = *(const float4*)(Aptr + k0);
        float4 bv = *(const float4*)(Bptr + (size_t)k0 * N);
        As[ac + 0][ar] = av.x;
        As[ac + 1][ar] = av.y;
        As[ac + 2][ar] = av.z;
        As[ac + 3][ar] = av.w;
        *(float4*)&Bs[br][bc] = bv;
        __syncthreads();
#pragma unroll
        for (int kk = 0; kk < 8; kk++) {
            float4 a0 = *(const float4*)&As[kk][ty * 8];
            float4 a1 = *(const float4*)&As[kk][ty * 8 + 4];
            float4 b0 = *(const float4*)&Bs[kk][tx * 8];
            float4 b1 = *(const float4*)&Bs[kk][tx * 8 + 4];
            float a[8] = {a0.x, a0.y, a0.z, a0.w, a1.x, a1.y, a1.z, a1.w};
            float bb[8] = {b0.x, b0.y, b0.z, b0.w, b1.x, b1.y, b1.z, b1.w};
#pragma unroll
            for (int i = 0; i < 8; i++)
#pragma unroll
                for (int j = 0; j < 8; j++)
                    acc[i][j] = fmaf(a[i], bb[j], acc[i][j]);
        }
        __syncthreads();
    }

#pragma unroll
    for (int i = 0; i < 8; i++) {
        int m = m0 + ty * 8 + i;
#pragma unroll
        for (int j2 = 0; j2 < 2; j2++) {
            int n = n0 + tx * 8 + j2 * 4;
            float4 v = make_float4(acc[i][j2 * 4 + 0], acc[i][j2 * 4 + 1],
                                   acc[i][j2 * 4 + 2], acc[i][j2 * 4 + 3]);
            if (MODE == 0) {
                *(float4*)&C[(size_t)m * N + n] = v;
            } else {
                int b = m >> 11, t = m & 2047;      // T = 2048
                int h = n >> 7, d = n & 127;        // D = 128
                size_t idx = (((size_t)(b * HH + h) * TT) + t) * DD + d;
                *(float4*)&C[idx] = v;
            }
        }
    }
}

// -------- gather RoPE, in place on [B,H,T,D], pos[B,T] ---------------------
__global__ void rope_apply_kernel(float* __restrict__ buf,
                                  const int* __restrict__ pos) {
    int row = blockIdx.x;                 // over B*H*T
    int d = threadIdx.x;                  // 0..127
    int t = row & (TT - 1);
    int b = row / (TT * HH);
    int p = pos[b * TT + t];
    size_t base = (size_t)row * DD;
    float v = buf[base + d];
    float o = buf[base + (d ^ 64)];
    __syncthreads();                      // all reads before any write
    float rot = (d < 64) ? -o : o;
    buf[base + d] = v * g_cos[(size_t)p * DD + d] + rot * g_sin[(size_t)p * DD + d];
}

// -------- fp32 flash attention: BQ=64, BK=64, D=128 ------------------------
// Q,K,V in [B,H,T,D]; Y written to [B,TQ,H*D]
__global__ __launch_bounds__(256, 2)
void flash_attn_kernel(const float* __restrict__ Q, const float* __restrict__ Kp,
                       const float* __restrict__ Vp,
                       float* __restrict__ Y) {
    extern __shared__ float sm[];
    float* Qs  = sm;                 // 64*128
    float* KVs = sm + 64 * 128;      // 64*132 (padded)
    float* Ps  = KVs + 64 * 132;     // 64*68  (padded)

    const int tid = threadIdx.x;
    const int bh = blockIdx.y;            // b*H + h
    const int b = bh >> 4;                // H = 16
    const int h = bh & 15;
    const int qt = blockIdx.x;

    const float* qbase = Q + ((size_t)bh * TQ + qt * 64) * DD;
    const float* kbase = Kp + (size_t)bh * TT * DD;
    const float* vbase = Vp + (size_t)bh * TT * DD;
    const unsigned char* mbase = g_mask_u8 + (size_t)b * TT;

    // load Q tile
    for (int i = tid; i < 64 * 32; i += 256) {
        int r = i >> 5, c4 = (i & 31) << 2;
        *(float4*)&Qs[r * 128 + c4] = *(const float4*)&qbase[(size_t)r * DD + c4];
    }

    const int tx = tid & 15, ty = tid >> 4;
    const float scale = 0.08838834764831845f;     // 1/sqrt(128)
    const float LOG2E = 1.4426950408889634f;

    float m_i[4], l_i[4], acc[4][8];
#pragma unroll
    for (int i = 0; i < 4; i++) {
        m_i[i] = -3.4e38f;
        l_i[i] = 0.0f;
#pragma unroll
        for (int j = 0; j < 8; j++) acc[i][j] = 0.0f;
    }

    for (int kt = 0; kt < TT / 64; kt++) {
        // load K tile
        for (int i = tid; i < 64 * 32; i += 256) {
            int r = i >> 5, c4 = (i & 31) << 2;
            *(float4*)&KVs[r * 132 + c4] =
                *(const float4*)&kbase[((size_t)kt * 64 + r) * DD + c4];
        }
        __syncthreads();

        // S = Q K^T (scaled), per-thread 4x4
        float s[4][4];
#pragma unroll
        for (int i = 0; i < 4; i++)
#pragma unroll
            for (int j = 0; j < 4; j++) s[i][j] = 0.0f;

#pragma unroll 8
        for (int d4 = 0; d4 < 32; d4++) {
            float4 kv[4];
#pragma unroll
            for (int j = 0; j < 4; j++)
                kv[j] = *(const float4*)&KVs[(tx * 4 + j) * 132 + d4 * 4];
#pragma unroll
            for (int i = 0; i < 4; i++) {
                float4 qv = *(const float4*)&Qs[(ty * 4 + i) * 128 + d4 * 4];
#pragma unroll
                for (int j = 0; j < 4; j++) {
                    s[i][j] = fmaf(qv.x, kv[j].x, s[i][j]);
                    s[i][j] = fmaf(qv.y, kv[j].y, s[i][j]);
                    s[i][j] = fmaf(qv.z, kv[j].z, s[i][j]);
                    s[i][j] = fmaf(qv.w, kv[j].w, s[i][j]);
                }
            }
        }

        // scale + mask (normalized uint8, nonzero => masked out)
        unsigned int mw = *(const unsigned int*)&mbase[kt * 64 + tx * 4];
#pragma unroll
        for (int j = 0; j < 4; j++) {
            bool mk = ((mw >> (8 * j)) & 0xFF) != 0;
#pragma unroll
            for (int i = 0; i < 4; i++)
                s[i][j] = mk ? -1e30f : s[i][j] * scale;
        }

        // online softmax
#pragma unroll
        for (int i = 0; i < 4; i++) {
            float rm = fmaxf(fmaxf(s[i][0], s[i][1]), fmaxf(s[i][2], s[i][3]));
#pragma unroll
            for (int off = 1; off < 16; off <<= 1)
                rm = fmaxf(rm, __shfl_xor_sync(0xffffffffu, rm, off));
            float mnew = fmaxf(m_i[i], rm);
            float alpha = exp2f((m_i[i] - mnew) * LOG2E);
            m_i[i] = mnew;
            float rs = 0.0f;
#pragma unroll
            for (int j = 0; j < 4; j++) {
                float p = exp2f((s[i][j] - mnew) * LOG2E);
                s[i][j] = p;
                rs += p;
            }
#pragma unroll
            for (int off = 1; off < 16; off <<= 1)
                rs += __shfl_xor_sync(0xffffffffu, rs, off);
            l_i[i] = l_i[i] * alpha + rs;
#pragma unroll
            for (int j = 0; j < 8; j++) acc[i][j] *= alpha;
        }

        // write P tile
#pragma unroll
        for (int i = 0; i < 4; i++)
#pragma unroll
            for (int j = 0; j < 4; j++)
                Ps[(ty * 4 + i) * 68 + tx * 4 + j] = s[i][j];
        __syncthreads();

        // load V tile into same buffer
        for (int i = tid; i < 64 * 32; i += 256) {
            int r = i >> 5, c4 = (i & 31) << 2;
            *(float4*)&KVs[r * 132 + c4] =
                *(const float4*)&vbase[((size_t)kt * 64 + r) * DD + c4];
        }
        __syncthreads();

        // O += P V
#pragma unroll 8
        for (int k = 0; k < 64; k++) {
            float pv[4];
#pragma unroll
            for (int i = 0; i < 4; i++) pv[i] = Ps[(ty * 4 + i) * 68 + k];
            float4 v0 = *(const float4*)&KVs[k * 132 + tx * 8];
            float4 v1 = *(const float4*)&KVs[k * 132 + tx * 8 + 4];
#pragma unroll
            for (int i = 0; i < 4; i++) {
                acc[i][0] = fmaf(pv[i], v0.x, acc[i][0]);
                acc[i][1] = fmaf(pv[i], v0.y, acc[i][1]);
                acc[i][2] = fmaf(pv[i], v0.z, acc[i][2]);
                acc[i][3] = fmaf(pv[i], v0.w, acc[i][3]);
                acc[i][4] = fmaf(pv[i], v1.x, acc[i][4]);
                acc[i][5] = fmaf(pv[i], v1.y, acc[i][5]);
                acc[i][6] = fmaf(pv[i], v1.z, acc[i][6]);
                acc[i][7] = fmaf(pv[i], v1.w, acc[i][7]);
            }
        }
        __syncthreads();
    }

    // epilogue: normalize + store to [B,TQ,H*D]
#pragma unroll
    for (int i = 0; i < 4; i++) {
        float inv = 1.0f / l_i[i];
        int q = qt * 64 + ty * 4 + i;
        size_t base = (((size_t)b * TQ + q) * HH + h) * DD + tx * 8;
        float4 o0 = make_float4(acc[i][0] * inv, acc[i][1] * inv,
                                acc[i][2] * inv, acc[i][3] * inv);
        float4 o1 = make_float4(acc[i][4] * inv, acc[i][5] * inv,
                                acc[i][6] * inv, acc[i][7] * inv);
        *(float4*)&Y[base] = o0;
        *(float4*)&Y[base + 4] = o1;
    }
}

// ---------------------------------------------------------------------------
extern "C" void kernel_launch(void* const* d_in, const int* in_sizes, int n_in,
                              void* d_out, int out_size) {
    const float* x     = (const float*)d_in[0];
    const float* xall  = (const float*)d_in[1];
    const int*   posx  = (const int*)d_in[2];
    const int*   posxa = (const int*)d_in[3];
    const void*  mask  = d_in[4];
    const float* Wq = (const float*)d_in[5];
    const float* Wk = (const float*)d_in[6];
    const float* Wv = (const float*)d_in[7];
    const float* Wo = (const float*)d_in[8];
    float* out = (float*)d_out;

    float *qptr, *kptr, *vptr, *yptr;
    cudaGetSymbolAddress((void**)&qptr, g_q);
    cudaGetSymbolAddress((void**)&kptr, g_k);
    cudaGetSymbolAddress((void**)&vptr, g_v);
    cudaGetSymbolAddress((void**)&yptr, g_y);

    const int smem_attn = (64 * 128 + 64 * 132 + 64 * 68) * sizeof(float);
    cudaFuncSetAttribute(flash_attn_kernel,
                         cudaFuncAttributeMaxDynamicSharedMemorySize, smem_attn);

    // 0. mask dtype detect + normalize to uint8
    mask_detect_kernel<<<1, 256>>>((const unsigned int*)mask);
    mask_convert_kernel<<<(BB * TT) / 256, 256>>>(mask);

    // 1. RoPE tables
    rope_tables_kernel<<<NBLOCK, DD>>>();

    // 2. QKV projections (M=8192, N=2048, K=2048), write [B,H,T,D]
    dim3 gemm_grid(HD / 128, (BB * TQ) / 128);
    sgemm_kernel<1><<<gemm_grid, 256>>>(x,    Wq, qptr, BB * TQ, HD, EE);
    sgemm_kernel<1><<<gemm_grid, 256>>>(xall, Wk, kptr, BB * TT, HD, EE);
    sgemm_kernel<1><<<gemm_grid, 256>>>(xall, Wv, vptr, BB * TT, HD, EE);

    // 3. RoPE on q, k
    rope_apply_kernel<<<BB * HH * TQ, DD>>>(qptr, posx);
    rope_apply_kernel<<<BB * HH * TT, DD>>>(kptr, posxa);

    // 4. flash attention -> y [B,TQ,H*D]
    dim3 attn_grid(TQ / 64, BB * HH);
    flash_attn_kernel<<<attn_grid, 256, smem_attn>>>(qptr, kptr, vptr, yptr);

    // 5. output projection -> d_out [B*TQ, E]
    dim3 ogrid(EE / 128, (BB * TQ) / 128);
    sgemm_kernel<0><<<ogrid, 256>>>(yptr, Wo, out, BB * TQ, EE, HD);
}

// round 3
// speedup vs baseline: 6.2059x; 6.2059x over previous
#include <cuda_runtime.h>
#include <cuda_bf16.h>
#include <math.h>
#include <stdint.h>

#define BB 4
#define TQ 2048
#define TT 2048
#define EE 2048
#define HH 16
#define DD 128
#define HD (HH*DD)
#define NBLOCK 4096

// -------- scratch --------
__device__ float g_q[(size_t)BB*HH*TQ*DD];     // [B,H,TQ,D]
__device__ float g_k[(size_t)BB*HH*TT*DD];     // [B,H,T,D]
__device__ float g_v[(size_t)BB*HH*TT*DD];     // [B,H,T,D]
__device__ float g_y[(size_t)BB*TQ*HD];        // [B,TQ,H*D]
__device__ float g_cos[(size_t)NBLOCK*DD];
__device__ float g_sin[(size_t)NBLOCK*DD];
__device__ unsigned char g_mask_u8[(size_t)BB*TT];
__device__ int g_mask_mode;

// -------- mma/ldmatrix helpers --------
__device__ __forceinline__ uint32_t smem_u32(const void* p) {
    return (uint32_t)__cvta_generic_to_shared(p);
}
__device__ __forceinline__ void ldm_x4(uint32_t* r, uint32_t addr) {
    asm volatile("ldmatrix.sync.aligned.m8n8.x4.shared.b16 {%0,%1,%2,%3}, [%4];\n"
                 : "=r"(r[0]), "=r"(r[1]), "=r"(r[2]), "=r"(r[3]) : "r"(addr));
}
__device__ __forceinline__ void ldm_x4_t(uint32_t* r, uint32_t addr) {
    asm volatile("ldmatrix.sync.aligned.m8n8.x4.trans.shared.b16 {%0,%1,%2,%3}, [%4];\n"
                 : "=r"(r[0]), "=r"(r[1]), "=r"(r[2]), "=r"(r[3]) : "r"(addr));
}
__device__ __forceinline__ void mma_bf16(float* c, const uint32_t* a, const uint32_t* b) {
    asm volatile("mma.sync.aligned.m16n8k16.row.col.f32.bf16.bf16.f32 "
                 "{%0,%1,%2,%3}, {%4,%5,%6,%7}, {%8,%9}, {%0,%1,%2,%3};\n"
                 : "+f"(c[0]), "+f"(c[1]), "+f"(c[2]), "+f"(c[3])
                 : "r"(a[0]), "r"(a[1]), "r"(a[2]), "r"(a[3]), "r"(b[0]), "r"(b[1]));
}
__device__ __forceinline__ void split_st(float f, __nv_bfloat16* hi, __nv_bfloat16* lo) {
    __nv_bfloat16 h = __float2bfloat16(f);
    *hi = h;
    *lo = __float2bfloat16(f - __bfloat162float(h));
}
__device__ __forceinline__ void split_pack(float a, float b, uint32_t& hi, uint32_t& lo) {
    __nv_bfloat16 ah = __float2bfloat16(a), bh = __float2bfloat16(b);
    float ar = a - __bfloat162float(ah), br = b - __bfloat162float(bh);
    __nv_bfloat162 h = __halves2bfloat162(ah, bh);
    __nv_bfloat162 l = __halves2bfloat162(__float2bfloat16(ar), __float2bfloat16(br));
    hi = *reinterpret_cast<uint32_t*>(&h);
    lo = *reinterpret_cast<uint32_t*>(&l);
}

// -------- mask dtype detection (bool may arrive as u8 / i32 / f32) ---------
__global__ void mask_detect_kernel(const unsigned int* __restrict__ m) {
    __shared__ int s_not01, s_notf;
    if (threadIdx.x == 0) { s_not01 = 0; s_notf = 0; }
    __syncthreads();
    int not01 = 0, notf = 0;
    for (int i = threadIdx.x; i < 2048; i += 256) {
        unsigned int w = m[i];
        if (w != 0u && w != 1u) not01 = 1;
        if (w != 0u && w != 0x3F800000u) notf = 1;
    }
    if (not01) atomicOr(&s_not01, 1);
    if (notf) atomicOr(&s_notf, 1);
    __syncthreads();
    if (threadIdx.x == 0) {
        int mode;
        if (!s_not01) mode = 1;
        else if (!s_notf) mode = 2;
        else mode = 0;
        g_mask_mode = mode;
    }
}

__global__ void mask_convert_kernel(const void* __restrict__ m) {
    int i = blockIdx.x * 256 + threadIdx.x;
    int mode = g_mask_mode;
    unsigned char v;
    if (mode == 1)      v = (((const int*)m)[i] != 0);
    else if (mode == 2) v = (((const float*)m)[i] != 0.0f);
    else                v = (((const unsigned char*)m)[i] != 0);
    g_mask_u8[i] = v;
}

// -------- RoPE tables --------
__global__ void rope_tables_kernel() {
    int p = blockIdx.x;
    int d = threadIdx.x;
    int j = d & 63;
    double inv = pow(10000.0, -((double)(2 * j)) / 128.0);
    float f = (float)p * (float)inv;
    g_cos[(size_t)p * DD + d] = cosf(f);
    g_sin[(size_t)p * DD + d] = sinf(f);
}

// -------- split-bf16 tensor GEMM: C[8192,2048] = A[8192,2048] @ W[2048,2048]
// MODE 0: row-major store. MODE 1: store to [B,H,T,D]
template <int MODE>
__global__ __launch_bounds__(256, 2)
void mma_gemm_kernel(const float* __restrict__ A, const float* __restrict__ W,
                     float* __restrict__ C) {
    const int M_ = 8192, N_ = 2048, K_ = 2048;
    __shared__ __align__(16) __nv_bfloat16 Ah[128][40];
    __shared__ __align__(16) __nv_bfloat16 Al[128][40];
    __shared__ __align__(16) __nv_bfloat16 Wh[32][136];
    __shared__ __align__(16) __nv_bfloat16 Wl[32][136];

    const int tid = threadIdx.x;
    const int lane = tid & 31, w = tid >> 5;
    const int wm = (w >> 1) * 32, wn = (w & 1) * 64;
    const int m0 = blockIdx.y * 128, n0 = blockIdx.x * 128;

    const int arow = tid >> 3, acol = (tid & 7) * 4;
    const int wrow = tid >> 6, wcol = (tid & 63) * 2;

    float acc[2][8][4];
#pragma unroll
    for (int mt = 0; mt < 2; mt++)
#pragma unroll
        for (int j = 0; j < 8; j++)
#pragma unroll
            for (int e = 0; e < 4; e++) acc[mt][j][e] = 0.0f;

    const int lr = lane & 7, lg = lane >> 3;

    for (int k0 = 0; k0 < K_; k0 += 32) {
        // prefetch to registers (overlaps with prior iter's MMA before sync)
        float4 av[4];
        float2 wv[8];
#pragma unroll
        for (int i = 0; i < 4; i++)
            av[i] = *(const float4*)&A[(size_t)(m0 + arow + i * 32) * K_ + k0 + acol];
#pragma unroll
        for (int i = 0; i < 8; i++)
            wv[i] = *(const float2*)&W[(size_t)(k0 + wrow + i * 4) * N_ + n0 + wcol];

        __syncthreads();
#pragma unroll
        for (int i = 0; i < 4; i++) {
            int r = arow + i * 32;
            split_st(av[i].x, &Ah[r][acol + 0], &Al[r][acol + 0]);
            split_st(av[i].y, &Ah[r][acol + 1], &Al[r][acol + 1]);
            split_st(av[i].z, &Ah[r][acol + 2], &Al[r][acol + 2]);
            split_st(av[i].w, &Ah[r][acol + 3], &Al[r][acol + 3]);
        }
#pragma unroll
        for (int i = 0; i < 8; i++) {
            int r = wrow + i * 4;
            split_st(wv[i].x, &Wh[r][wcol + 0], &Wl[r][wcol + 0]);
            split_st(wv[i].y, &Wh[r][wcol + 1], &Wl[r][wcol + 1]);
        }
        __syncthreads();

#pragma unroll
        for (int ks = 0; ks < 2; ks++) {
            const int kk = ks * 16;
            uint32_t ah[2][4], al[2][4];
#pragma unroll
            for (int mt = 0; mt < 2; mt++) {
                int row = wm + mt * 16 + lr + (lg & 1) * 8;
                int col = kk + (lg >> 1) * 8;
                ldm_x4(ah[mt], smem_u32(&Ah[row][col]));
                ldm_x4(al[mt], smem_u32(&Al[row][col]));
            }
#pragma unroll
            for (int jp = 0; jp < 4; jp++) {
                int brow = kk + lr + (lg & 1) * 8;
                int bcol = wn + jp * 16 + (lg >> 1) * 8;
                uint32_t bh[4], bl[4];
                ldm_x4_t(bh, smem_u32(&Wh[brow][bcol]));
                ldm_x4_t(bl, smem_u32(&Wl[brow][bcol]));
#pragma unroll
                for (int mt = 0; mt < 2; mt++) {
                    mma_bf16(acc[mt][2 * jp], ah[mt], bh);
                    mma_bf16(acc[mt][2 * jp], ah[mt], bl);
                    mma_bf16(acc[mt][2 * jp], al[mt], bh);
                    mma_bf16(acc[mt][2 * jp + 1], ah[mt], bh + 2);
                    mma_bf16(acc[mt][2 * jp + 1], ah[mt], bl + 2);
                    mma_bf16(acc[mt][2 * jp + 1], al[mt], bh + 2);
                }
            }
        }
    }

    // epilogue
#pragma unroll
    for (int mt = 0; mt < 2; mt++) {
        int r0 = m0 + wm + mt * 16 + (lane >> 2);
        int r1 = r0 + 8;
#pragma unroll
        for (int j = 0; j < 8; j++) {
            int c = n0 + wn + j * 8 + (lane & 3) * 2;
            float2 v0 = make_float2(acc[mt][j][0], acc[mt][j][1]);
            float2 v1 = make_float2(acc[mt][j][2], acc[mt][j][3]);
            if (MODE == 0) {
                *(float2*)&C[(size_t)r0 * N_ + c] = v0;
                *(float2*)&C[(size_t)r1 * N_ + c] = v1;
            } else {
                int h = c >> 7, d = c & 127;
                int b0_ = r0 >> 11, t0 = r0 & 2047;
                int b1_ = r1 >> 11, t1 = r1 & 2047;
                *(float2*)&C[(((size_t)(b0_ * HH + h) * TT) + t0) * DD + d] = v0;
                *(float2*)&C[(((size_t)(b1_ * HH + h) * TT) + t1) * DD + d] = v1;
            }
        }
    }
}

// -------- gather RoPE, in place on [B,H,T,D], pos[B,T] ---------------------
__global__ void rope_apply_kernel(float* __restrict__ buf,
                                  const int* __restrict__ pos) {
    int row = blockIdx.x;
    int d = threadIdx.x;
    int t = row & (TT - 1);
    int b = row / (TT * HH);
    int p = pos[b * TT + t];
    size_t base = (size_t)row * DD;
    float v = buf[base + d];
    float o = buf[base + (d ^ 64)];
    __syncthreads();
    float rot = (d < 64) ? -o : o;
    buf[base + d] = v * g_cos[(size_t)p * DD + d] + rot * g_sin[(size_t)p * DD + d];
}

// -------- split-bf16 tensor-core flash attention: BQ=64, BK=64, D=128 ------
// 128 threads = 4 warps, each warp owns 16 q-rows.
#define FSTR 136
__global__ __launch_bounds__(128)
void flash_mma_kernel(const float* __restrict__ Q, const float* __restrict__ Kp,
                      const float* __restrict__ Vp, float* __restrict__ Y) {
    extern __shared__ __align__(16) __nv_bfloat16 fsm[];
    __nv_bfloat16* Kh = fsm;
    __nv_bfloat16* Kl = fsm + 64 * FSTR;
    __nv_bfloat16* Vh = fsm + 2 * 64 * FSTR;
    __nv_bfloat16* Vl = fsm + 3 * 64 * FSTR;
    unsigned char* mbuf = (unsigned char*)(fsm + 4 * 64 * FSTR);

    const int tid = threadIdx.x;
    const int lane = tid & 31, w = tid >> 5;
    const int lr = lane & 7, lg = lane >> 3;
    const int bh = blockIdx.y;
    const int b = bh >> 4, h = bh & 15;
    const int qt = blockIdx.x;

    const float* qbase = Q + ((size_t)bh * TQ + qt * 64) * DD;
    const float* kbase = Kp + (size_t)bh * TT * DD;
    const float* vbase = Vp + (size_t)bh * TT * DD;
    const unsigned char* mbase = g_mask_u8 + (size_t)b * TT;

    // ---- stage Q through V buffers, build register fragments ----
    {
#pragma unroll
        for (int i = 0; i < 16; i++) {
            int f4 = i * 128 + tid;               // 0..2047
            int r = f4 >> 5, c = (f4 & 31) * 4;
            float4 v = *(const float4*)&qbase[(size_t)r * DD + c];
            split_st(v.x, &Vh[r * FSTR + c + 0], &Vl[r * FSTR + c + 0]);
            split_st(v.y, &Vh[r * FSTR + c + 1], &Vl[r * FSTR + c + 1]);
            split_st(v.z, &Vh[r * FSTR + c + 2], &Vl[r * FSTR + c + 2]);
            split_st(v.w, &Vh[r * FSTR + c + 3], &Vl[r * FSTR + c + 3]);
        }
    }
    __syncthreads();

    uint32_t qh[8][4], ql[8][4];
#pragma unroll
    for (int ks = 0; ks < 8; ks++) {
        int row = w * 16 + lr + (lg & 1) * 8;
        int col = ks * 16 + (lg >> 1) * 8;
        ldm_x4(qh[ks], smem_u32(&Vh[row * FSTR + col]));
        ldm_x4(ql[ks], smem_u32(&Vl[row * FSTR + col]));
    }

    float mrow[2] = {-3.4e38f, -3.4e38f};
    float lrow[2] = {0.0f, 0.0f};
    float oc[16][4];
#pragma unroll
    for (int j = 0; j < 16; j++)
#pragma unroll
        for (int e = 0; e < 4; e++) oc[j][e] = 0.0f;

    const float scale = 0.08838834764831845f;
    const float LOG2E = 1.4426950408889634f;
    const int cb = (lane & 3) * 2;

    for (int kt = 0; kt < TT / 64; kt++) {
        __syncthreads();
        // load + convert K, V tiles
        const float* kb = kbase + (size_t)kt * 64 * DD;
        const float* vb = vbase + (size_t)kt * 64 * DD;
#pragma unroll
        for (int i = 0; i < 16; i++) {
            int f4 = i * 128 + tid;
            int r = f4 >> 5, c = (f4 & 31) * 4;
            float4 kv = *(const float4*)&kb[(size_t)r * DD + c];
            float4 vv = *(const float4*)&vb[(size_t)r * DD + c];
            split_st(kv.x, &Kh[r * FSTR + c + 0], &Kl[r * FSTR + c + 0]);
            split_st(kv.y, &Kh[r * FSTR + c + 1], &Kl[r * FSTR + c + 1]);
            split_st(kv.z, &Kh[r * FSTR + c + 2], &Kl[r * FSTR + c + 2]);
            split_st(kv.w, &Kh[r * FSTR + c + 3], &Kl[r * FSTR + c + 3]);
            split_st(vv.x, &Vh[r * FSTR + c + 0], &Vl[r * FSTR + c + 0]);
            split_st(vv.y, &Vh[r * FSTR + c + 1], &Vl[r * FSTR + c + 1]);
            split_st(vv.z, &Vh[r * FSTR + c + 2], &Vl[r * FSTR + c + 2]);
            split_st(vv.w, &Vh[r * FSTR + c + 3], &Vl[r * FSTR + c + 3]);
        }
        if (tid < 16)
            *(uint32_t*)(mbuf + tid * 4) = *(const uint32_t*)(mbase + kt * 64 + tid * 4);
        __syncthreads();

        // ---- S = Q K^T ----
        float sc[8][4];
#pragma unroll
        for (int j = 0; j < 8; j++)
#pragma unroll
            for (int e = 0; e < 4; e++) sc[j][e] = 0.0f;

#pragma unroll
        for (int ks = 0; ks < 8; ks++) {
#pragma unroll
            for (int jp = 0; jp < 4; jp++) {
                int krow = jp * 16 + lr + (lg >> 1) * 8;   // key index
                int kcol = ks * 16 + (lg & 1) * 8;         // d index
                uint32_t bh_[4], bl_[4];
                ldm_x4(bh_, smem_u32(&Kh[krow * FSTR + kcol]));
                ldm_x4(bl_, smem_u32(&Kl[krow * FSTR + kcol]));
                mma_bf16(sc[2 * jp], qh[ks], bh_);
                mma_bf16(sc[2 * jp], qh[ks], bl_);
                mma_bf16(sc[2 * jp], ql[ks], bh_);
                mma_bf16(sc[2 * jp + 1], qh[ks], bh_ + 2);
                mma_bf16(sc[2 * jp + 1], qh[ks], bl_ + 2);
                mma_bf16(sc[2 * jp + 1], ql[ks], bh_ + 2);
            }
        }

        // ---- mask + scale ----
#pragma unroll
        for (int j = 0; j < 8; j++) {
            bool mk0 = mbuf[j * 8 + cb] != 0;
            bool mk1 = mbuf[j * 8 + cb + 1] != 0;
            sc[j][0] = mk0 ? -1e30f : sc[j][0] * scale;
            sc[j][1] = mk1 ? -1e30f : sc[j][1] * scale;
            sc[j][2] = mk0 ? -1e30f : sc[j][2] * scale;
            sc[j][3] = mk1 ? -1e30f : sc[j][3] * scale;
        }

        // ---- online softmax (2 rows per thread) ----
#pragma unroll
        for (int rr = 0; rr < 2; rr++) {
            float mx = -3.4e38f;
#pragma unroll
            for (int j = 0; j < 8; j++)
                mx = fmaxf(mx, fmaxf(sc[j][2 * rr], sc[j][2 * rr + 1]));
            mx = fmaxf(mx, __shfl_xor_sync(0xffffffffu, mx, 1));
            mx = fmaxf(mx, __shfl_xor_sync(0xffffffffu, mx, 2));
            float mnew = fmaxf(mrow[rr], mx);
            float alpha = exp2f((mrow[rr] - mnew) * LOG2E);
            mrow[rr] = mnew;
            float s = 0.0f;
#pragma unroll
            for (int j = 0; j < 8; j++) {
                float p0 = exp2f((sc[j][2 * rr] - mnew) * LOG2E);
                float p1 = exp2f((sc[j][2 * rr + 1] - mnew) * LOG2E);
                sc[j][2 * rr] = p0;
                sc[j][2 * rr + 1] = p1;
                s += p0 + p1;
            }
            s += __shfl_xor_sync(0xffffffffu, s, 1);
            s += __shfl_xor_sync(0xffffffffu, s, 2);
            lrow[rr] = lrow[rr] * alpha + s;
#pragma unroll
            for (int j = 0; j < 16; j++) {
                oc[j][2 * rr] *= alpha;
                oc[j][2 * rr + 1] *= alpha;
            }
        }

        // ---- O += P V ----
#pragma unroll
        for (int ks = 0; ks < 4; ks++) {
            uint32_t ph[4], pl[4];
            split_pack(sc[2 * ks][0], sc[2 * ks][1], ph[0], pl[0]);
            split_pack(sc[2 * ks][2], sc[2 * ks][3], ph[1], pl[1]);
            split_pack(sc[2 * ks + 1][0], sc[2 * ks + 1][1], ph[2], pl[2]);
            split_pack(sc[2 * ks + 1][2], sc[2 * ks + 1][3], ph[3], pl[3]);
#pragma unroll
            for (int jp = 0; jp < 8; jp++) {
                int vrow = ks * 16 + lr + (lg & 1) * 8;    // key index
                int vcol = jp * 16 + (lg >> 1) * 8;        // d index
                uint32_t vh_[4], vl_[4];
                ldm_x4_t(vh_, smem_u32(&Vh[vrow * FSTR + vcol]));
                ldm_x4_t(vl_, smem_u32(&Vl[vrow * FSTR + vcol]));
                mma_bf16(oc[2 * jp], ph, vh_);
                mma_bf16(oc[2 * jp], ph, vl_);
                mma_bf16(oc[2 * jp], pl, vh_);
                mma_bf16(oc[2 * jp + 1], ph, vh_ + 2);
                mma_bf16(oc[2 * jp + 1], ph, vl_ + 2);
                mma_bf16(oc[2 * jp + 1], pl, vh_ + 2);
            }
        }
    }

    // ---- epilogue: normalize + store to [B,TQ,H*D] ----
    float inv0 = 1.0f / lrow[0];
    float inv1 = 1.0f / lrow[1];
    int q0 = qt * 64 + w * 16 + (lane >> 2);
    int q1 = q0 + 8;
    size_t base0 = ((size_t)b * TQ + q0) * HD + h * DD;
    size_t base1 = ((size_t)b * TQ + q1) * HD + h * DD;
#pragma unroll
    for (int j = 0; j < 16; j++) {
        int d = j * 8 + cb;
        *(float2*)&Y[base0 + d] = make_float2(oc[j][0] * inv0, oc[j][1] * inv0);
        *(float2*)&Y[base1 + d] = make_float2(oc[j][2] * inv1, oc[j][3] * inv1);
    }
}

// ---------------------------------------------------------------------------
extern "C" void kernel_launch(void* const* d_in, const int* in_sizes, int n_in,
                              void* d_out, int out_size) {
    const float* x     = (const float*)d_in[0];
    const float* xall  = (const float*)d_in[1];
    const int*   posx  = (const int*)d_in[2];
    const int*   posxa = (const int*)d_in[3];
    const void*  mask  = d_in[4];
    const float* Wq = (const float*)d_in[5];
    const float* Wk = (const float*)d_in[6];
    const float* Wv = (const float*)d_in[7];
    const float* Wo = (const float*)d_in[8];
    float* out = (float*)d_out;

    float *qptr, *kptr, *vptr, *yptr;
    cudaGetSymbolAddress((void**)&qptr, g_q);
    cudaGetSymbolAddress((void**)&kptr, g_k);
    cudaGetSymbolAddress((void**)&vptr, g_v);
    cudaGetSymbolAddress((void**)&yptr, g_y);

    const int smem_flash = 4 * 64 * FSTR * (int)sizeof(__nv_bfloat16) + 64;
    cudaFuncSetAttribute(flash_mma_kernel,
                         cudaFuncAttributeMaxDynamicSharedMemorySize, smem_flash);

    // 0. mask dtype detect + normalize to uint8
    mask_detect_kernel<<<1, 256>>>((const unsigned int*)mask);
    mask_convert_kernel<<<(BB * TT) / 256, 256>>>(mask);

    // 1. RoPE tables
    rope_tables_kernel<<<NBLOCK, DD>>>();

    // 2. QKV projections (tensor cores, split-bf16), write [B,H,T,D]
    dim3 gemm_grid(EE / 128, (BB * TQ) / 128);
    mma_gemm_kernel<1><<<gemm_grid, 256>>>(x,    Wq, qptr);
    mma_gemm_kernel<1><<<gemm_grid, 256>>>(xall, Wk, kptr);
    mma_gemm_kernel<1><<<gemm_grid, 256>>>(xall, Wv, vptr);

    // 3. RoPE on q, k
    rope_apply_kernel<<<BB * HH * TQ, DD>>>(qptr, posx);
    rope_apply_kernel<<<BB * HH * TT, DD>>>(kptr, posxa);

    // 4. flash attention (tensor cores, split-bf16) -> y [B,TQ,H*D]
    dim3 attn_grid(TQ / 64, BB * HH);
    flash_mma_kernel<<<attn_grid, 128, smem_flash>>>(qptr, kptr, vptr, yptr);

    // 5. output projection -> d_out
    mma_gemm_kernel<0><<<gemm_grid, 256>>>(yptr, Wo, out);
}

// round 5
// speedup vs baseline: 6.4858x; 1.0451x over previous
#include <cuda_runtime.h>
#include <cuda_bf16.h>
#include <math.h>
#include <stdint.h>

typedef __nv_bfloat16 bf16;

#define BB 4
#define TQ 2048
#define TT 2048
#define EE 2048
#define HH 16
#define DD 128
#define HD (HH*DD)
#define NBLOCK 4096
#define MM 8192
#define KK 2048
#define NN 2048

// -------- scratch --------
__device__ float g_q[(size_t)BB*HH*TQ*DD];
__device__ float g_k[(size_t)BB*HH*TT*DD];
__device__ float g_cos[(size_t)NBLOCK*DD];
__device__ float g_sin[(size_t)NBLOCK*DD];
__device__ unsigned char g_mask_u8[(size_t)BB*TT];
__device__ int g_mask_mode;

__device__ bf16 g_xh[(size_t)MM*KK],  g_xl[(size_t)MM*KK];
__device__ bf16 g_ah[(size_t)MM*KK],  g_al[(size_t)MM*KK];
__device__ bf16 g_qh[(size_t)MM*KK],  g_ql[(size_t)MM*KK];
__device__ bf16 g_kh[(size_t)MM*KK],  g_kl[(size_t)MM*KK];
__device__ bf16 g_vh[(size_t)MM*KK],  g_vl[(size_t)MM*KK];
__device__ bf16 g_yh[(size_t)MM*KK],  g_yl[(size_t)MM*KK];
__device__ bf16 g_wqh[(size_t)KK*NN], g_wql[(size_t)KK*NN];
__device__ bf16 g_wkh[(size_t)KK*NN], g_wkl[(size_t)KK*NN];
__device__ bf16 g_wvh[(size_t)KK*NN], g_wvl[(size_t)KK*NN];
__device__ bf16 g_woh[(size_t)KK*NN], g_wol[(size_t)KK*NN];

// -------- helpers --------
__device__ __forceinline__ uint32_t smem_u32(const void* p) {
    return (uint32_t)__cvta_generic_to_shared(p);
}
__device__ __forceinline__ void cpa16(uint32_t s, const void* g) {
    asm volatile("cp.async.cg.shared.global [%0], [%1], 16;\n" :: "r"(s), "l"(g));
}
__device__ __forceinline__ void cpa4(uint32_t s, const void* g) {
    asm volatile("cp.async.ca.shared.global [%0], [%1], 4;\n" :: "r"(s), "l"(g));
}
#define CP_COMMIT() asm volatile("cp.async.commit_group;" ::: "memory")
#define CP_WAIT1() asm volatile("cp.async.wait_group 1;" ::: "memory")
#define CP_WAIT0() asm volatile("cp.async.wait_group 0;" ::: "memory")

__device__ __forceinline__ void ldm_x4(uint32_t* r, uint32_t addr) {
    asm volatile("ldmatrix.sync.aligned.m8n8.x4.shared.b16 {%0,%1,%2,%3}, [%4];\n"
                 : "=r"(r[0]), "=r"(r[1]), "=r"(r[2]), "=r"(r[3]) : "r"(addr));
}
__device__ __forceinline__ void ldm_x4_t(uint32_t* r, uint32_t addr) {
    asm volatile("ldmatrix.sync.aligned.m8n8.x4.trans.shared.b16 {%0,%1,%2,%3}, [%4];\n"
                 : "=r"(r[0]), "=r"(r[1]), "=r"(r[2]), "=r"(r[3]) : "r"(addr));
}
__device__ __forceinline__ void mma_bf16(float* c, const uint32_t* a, const uint32_t* b) {
    asm volatile("mma.sync.aligned.m16n8k16.row.col.f32.bf16.bf16.f32 "
                 "{%0,%1,%2,%3}, {%4,%5,%6,%7}, {%8,%9}, {%0,%1,%2,%3};\n"
                 : "+f"(c[0]), "+f"(c[1]), "+f"(c[2]), "+f"(c[3])
                 : "r"(a[0]), "r"(a[1]), "r"(a[2]), "r"(a[3]), "r"(b[0]), "r"(b[1]));
}
__device__ __forceinline__ void split_st(float f, bf16* hi, bf16* lo) {
    bf16 h = __float2bfloat16(f);
    *hi = h;
    *lo = __float2bfloat16(f - __bfloat162float(h));
}
__device__ __forceinline__ void split2(float f, bf16& h, bf16& l) {
    h = __float2bfloat16(f);
    l = __float2bfloat16(f - __bfloat162float(h));
}
__device__ __forceinline__ void split_pack(float a, float b, uint32_t& hi, uint32_t& lo) {
    bf16 ah = __float2bfloat16(a), bh = __float2bfloat16(b);
    float ar = a - __bfloat162float(ah), br = b - __bfloat162float(bh);
    __nv_bfloat162 h = __halves2bfloat162(ah, bh);
    __nv_bfloat162 l = __halves2bfloat162(__float2bfloat16(ar), __float2bfloat16(br));
    hi = *reinterpret_cast<uint32_t*>(&h);
    lo = *reinterpret_cast<uint32_t*>(&l);
}

// -------- mask dtype detection + normalize ---------------------------------
__global__ void mask_detect_kernel(const unsigned int* __restrict__ m) {
    __shared__ int s_not01, s_notf;
    if (threadIdx.x == 0) { s_not01 = 0; s_notf = 0; }
    __syncthreads();
    int not01 = 0, notf = 0;
    for (int i = threadIdx.x; i < 2048; i += 256) {
        unsigned int w = m[i];
        if (w != 0u && w != 1u) not01 = 1;
        if (w != 0u && w != 0x3F800000u) notf = 1;
    }
    if (not01) atomicOr(&s_not01, 1);
    if (notf) atomicOr(&s_notf, 1);
    __syncthreads();
    if (threadIdx.x == 0) {
        int mode;
        if (!s_not01) mode = 1;
        else if (!s_notf) mode = 2;
        else mode = 0;
        g_mask_mode = mode;
    }
}
__global__ void mask_convert_kernel(const void* __restrict__ m) {
    int i = blockIdx.x * 256 + threadIdx.x;
    int mode = g_mask_mode;
    unsigned char v;
    if (mode == 1)      v = (((const int*)m)[i] != 0);
    else if (mode == 2) v = (((const float*)m)[i] != 0.0f);
    else                v = (((const unsigned char*)m)[i] != 0);
    g_mask_u8[i] = v;
}

// -------- RoPE tables --------
__global__ void rope_tables_kernel() {
    int p = blockIdx.x;
    int d = threadIdx.x;
    int j = d & 63;
    double inv = pow(10000.0, -((double)(2 * j)) / 128.0);
    float f = (float)p * (float)inv;
    g_cos[(size_t)p * DD + d] = cosf(f);
    g_sin[(size_t)p * DD + d] = sinf(f);
}

// -------- fp32 -> split bf16 ----------------------------------------------
__global__ void split_convert_kernel(const float* __restrict__ in,
                                     bf16* __restrict__ hi, bf16* __restrict__ lo) {
    size_t i = ((size_t)blockIdx.x * 256 + threadIdx.x) * 4;
    float4 v = *(const float4*)(in + i);
    bf16 h0, h1, h2, h3, l0, l1, l2, l3;
    split2(v.x, h0, l0); split2(v.y, h1, l1);
    split2(v.z, h2, l2); split2(v.w, h3, l3);
    __nv_bfloat162 hp0 = __halves2bfloat162(h0, h1), hp1 = __halves2bfloat162(h2, h3);
    __nv_bfloat162 lp0 = __halves2bfloat162(l0, l1), lp1 = __halves2bfloat162(l2, l3);
    *(uint2*)(hi + i) = make_uint2(*(uint32_t*)&hp0, *(uint32_t*)&hp1);
    *(uint2*)(lo + i) = make_uint2(*(uint32_t*)&lp0, *(uint32_t*)&lp1);
}

// -------- gather RoPE on fp32 [B,H,T,D] -> split bf16, optional scale ------
__global__ void rope_split_kernel(const float* __restrict__ buf,
                                  const int* __restrict__ pos,
                                  bf16* __restrict__ oh, bf16* __restrict__ ol,
                                  float fac) {
    int row = blockIdx.x;
    int d = threadIdx.x;
    int t = row & (TT - 1);
    int b = row / (TT * HH);
    int p = pos[b * TT + t];
    size_t base = (size_t)row * DD;
    float v = buf[base + d];
    float o = buf[base + (d ^ 64)];
    float rot = (d < 64) ? -o : o;
    float r = (v * g_cos[(size_t)p * DD + d] + rot * g_sin[(size_t)p * DD + d]) * fac;
    split_st(r, oh + base + d, ol + base + d);
}

// -------- HMMA split-bf16 GEMM: C[8192,2048] = A[8192,2048] @ W[2048,2048] -
// Pre-split bf16 inputs, 128x128 tile, 2-stage cp.async, 256 threads.
// MODE 0: fp32 row-major. MODE 1: fp32 [B,H,T,D]. MODE 2: split bf16 [B,H,T,D]
struct GStage {
    bf16 ah[128 * 40];
    bf16 al[128 * 40];
    bf16 wh[32 * 136];
    bf16 wl[32 * 136];
};

template <int MODE>
__global__ __launch_bounds__(256, 2)
void hmma_gemm(const bf16* __restrict__ Ah, const bf16* __restrict__ Al,
               const bf16* __restrict__ Wh, const bf16* __restrict__ Wl,
               float* __restrict__ C, bf16* __restrict__ Oh, bf16* __restrict__ Ol) {
    extern __shared__ __align__(16) char gsm[];
    GStage* st = (GStage*)gsm;
    const int tid = threadIdx.x, lane = tid & 31, w = tid >> 5;
    const int wm = (w & 3) * 32, wn = (w >> 2) * 64;
    const int m0 = blockIdx.y * 128, n0 = blockIdx.x * 128;
    const int lr = lane & 7, lg = lane >> 3;

    float acc[2][8][4];
#pragma unroll
    for (int mt = 0; mt < 2; mt++)
#pragma unroll
        for (int j = 0; j < 8; j++)
#pragma unroll
            for (int e = 0; e < 4; e++) acc[mt][j][e] = 0.0f;

#define G_LOAD(s, k0) do { \
    _Pragma("unroll") \
    for (int j = 0; j < 2; j++) { \
        int idx = j * 256 + tid; int r = idx >> 2, c = idx & 3; \
        size_t g = (size_t)(m0 + r) * KK + (k0) + c * 8; \
        cpa16(smem_u32(&st[s].ah[r * 40 + c * 8]), Ah + g); \
        cpa16(smem_u32(&st[s].al[r * 40 + c * 8]), Al + g); \
    } \
    _Pragma("unroll") \
    for (int j = 0; j < 2; j++) { \
        int idx = j * 256 + tid; int r = idx >> 4, c = idx & 15; \
        size_t g = (size_t)((k0) + r) * NN + n0 + c * 8; \
        cpa16(smem_u32(&st[s].wh[r * 136 + c * 8]), Wh + g); \
        cpa16(smem_u32(&st[s].wl[r * 136 + c * 8]), Wl + g); \
    } \
    CP_COMMIT(); } while (0)

    G_LOAD(0, 0);
    G_LOAD(1, 32);

    for (int i = 0; i < 64; i++) {
        if (i < 63) CP_WAIT1(); else CP_WAIT0();
        __syncthreads();
        GStage* cs = &st[i & 1];
#pragma unroll
        for (int ks = 0; ks < 2; ks++) {
            const int kk = ks * 16;
            uint32_t ahf[2][4], alf[2][4];
#pragma unroll
            for (int mt = 0; mt < 2; mt++) {
                int row = wm + mt * 16 + lr + (lg & 1) * 8;
                int col = kk + (lg >> 1) * 8;
                ldm_x4(ahf[mt], smem_u32(&cs->ah[row * 40 + col]));
                ldm_x4(alf[mt], smem_u32(&cs->al[row * 40 + col]));
            }
#pragma unroll
            for (int jp = 0; jp < 4; jp++) {
                int brow = kk + lr + (lg & 1) * 8;
                int bcol = wn + jp * 16 + (lg >> 1) * 8;
                uint32_t bh[4], bl[4];
                ldm_x4_t(bh, smem_u32(&cs->wh[brow * 136 + bcol]));
                ldm_x4_t(bl, smem_u32(&cs->wl[brow * 136 + bcol]));
#pragma unroll
                for (int mt = 0; mt < 2; mt++) {
                    mma_bf16(acc[mt][2 * jp], ahf[mt], bh);
                    mma_bf16(acc[mt][2 * jp], ahf[mt], bl);
                    mma_bf16(acc[mt][2 * jp], alf[mt], bh);
                    mma_bf16(acc[mt][2 * jp + 1], ahf[mt], bh + 2);
                    mma_bf16(acc[mt][2 * jp + 1], ahf[mt], bl + 2);
                    mma_bf16(acc[mt][2 * jp + 1], alf[mt], bh + 2);
                }
            }
        }
        __syncthreads();
        if (i + 2 < 64) G_LOAD(i & 1, (i + 2) * 32);
    }
#undef G_LOAD

    // epilogue
#pragma unroll
    for (int mt = 0; mt < 2; mt++) {
        int r0 = m0 + wm + mt * 16 + (lane >> 2);
        int r1 = r0 + 8;
#pragma unroll
        for (int j = 0; j < 8; j++) {
            int c = n0 + wn + j * 8 + (lane & 3) * 2;
            float2 v0 = make_float2(acc[mt][j][0], acc[mt][j][1]);
            float2 v1 = make_float2(acc[mt][j][2], acc[mt][j][3]);
            if (MODE == 0) {
                *(float2*)&C[(size_t)r0 * NN + c] = v0;
                *(float2*)&C[(size_t)r1 * NN + c] = v1;
            } else {
                int h = c >> 7, d = c & 127;
                int b0_ = r0 >> 11, t0 = r0 & 2047;
                int b1_ = r1 >> 11, t1 = r1 & 2047;
                size_t o0 = (((size_t)(b0_ * HH + h) * TT) + t0) * DD + d;
                size_t o1 = (((size_t)(b1_ * HH + h) * TT) + t1) * DD + d;
                if (MODE == 1) {
                    *(float2*)&C[o0] = v0;
                    *(float2*)&C[o1] = v1;
                } else {
                    bf16 h0, l0, h1, l1;
                    split2(v0.x, h0, l0); split2(v0.y, h1, l1);
                    *(__nv_bfloat162*)(Oh + o0) = __halves2bfloat162(h0, h1);
                    *(__nv_bfloat162*)(Ol + o0) = __halves2bfloat162(l0, l1);
                    split2(v1.x, h0, l0); split2(v1.y, h1, l1);
                    *(__nv_bfloat162*)(Oh + o1) = __halves2bfloat162(h0, h1);
                    *(__nv_bfloat162*)(Ol + o1) = __halves2bfloat162(l0, l1);
                }
            }
        }
    }
}

// -------- flash attention: BQ=128, BK=64, 256 threads, split-bf16 HMMA -----
// q pre-scaled by (1/sqrt(D))*log2(e): logits arrive in log2 domain.
struct FStage {
    bf16 kh[64 * 136];
    bf16 kl[64 * 136];
    bf16 vh[64 * 136];
    bf16 vl[64 * 136];
    unsigned char mk[64];
};

__global__ __launch_bounds__(256, 1)
void flash_kernel(const bf16* __restrict__ qh, const bf16* __restrict__ ql,
                  const bf16* __restrict__ kh, const bf16* __restrict__ kl,
                  const bf16* __restrict__ vh, const bf16* __restrict__ vl,
                  bf16* __restrict__ yh, bf16* __restrict__ yl) {
    extern __shared__ __align__(16) char fsm[];
    FStage* st = (FStage*)fsm;
    const int tid = threadIdx.x, lane = tid & 31, w = tid >> 5;
    const int lr = lane & 7, lg = lane >> 3;
    const int bh = blockIdx.y, b = bh >> 4, h = bh & 15, qt = blockIdx.x;
    const size_t qoff = ((size_t)bh * TQ + qt * 128) * DD;
    const size_t koff = (size_t)bh * TT * DD;
    const unsigned char* mrow = g_mask_u8 + (size_t)b * TT;

    // ---- stage Q (128x128) through st[0], build register fragments ----
#pragma unroll
    for (int j = 0; j < 8; j++) {
        int idx = j * 256 + tid;
        int r = idx >> 4, c = (idx & 15) * 8;
        bf16* dh = (r < 64) ? &st[0].kh[r * 136 + c] : &st[0].vh[(r - 64) * 136 + c];
        bf16* dl = (r < 64) ? &st[0].kl[r * 136 + c] : &st[0].vl[(r - 64) * 136 + c];
        cpa16(smem_u32(dh), qh + qoff + (size_t)r * DD + c);
        cpa16(smem_u32(dl), ql + qoff + (size_t)r * DD + c);
    }
    CP_COMMIT();
    CP_WAIT0();
    __syncthreads();

    uint32_t qfh[8][4], qfl[8][4];
    {
        const bf16* qsh = (w < 4) ? st[0].kh : st[0].vh;
        const bf16* qsl = (w < 4) ? st[0].kl : st[0].vl;
        int qrb = (w & 3) * 16;
#pragma unroll
        for (int ks = 0; ks < 8; ks++) {
            int row = qrb + lr + (lg & 1) * 8;
            int col = ks * 16 + (lg >> 1) * 8;
            ldm_x4(qfh[ks], smem_u32(&qsh[row * 136 + col]));
            ldm_x4(qfl[ks], smem_u32(&qsl[row * 136 + col]));
        }
    }
    __syncthreads();

    float m_i[2] = {-3.4e38f, -3.4e38f};
    float l_i[2] = {0.0f, 0.0f};
    float oc[16][4];
#pragma unroll
    for (int j = 0; j < 16; j++)
#pragma unroll
        for (int e = 0; e < 4; e++) oc[j][e] = 0.0f;

#define F_LOAD(s, kt) do { \
    _Pragma("unroll") \
    for (int j = 0; j < 4; j++) { \
        int idx = j * 256 + tid; int r = idx >> 4, c = (idx & 15) * 8; \
        size_t g = koff + ((size_t)(kt) * 64 + r) * DD + c; \
        cpa16(smem_u32(&st[s].kh[r * 136 + c]), kh + g); \
        cpa16(smem_u32(&st[s].kl[r * 136 + c]), kl + g); \
        cpa16(smem_u32(&st[s].vh[r * 136 + c]), vh + g); \
        cpa16(smem_u32(&st[s].vl[r * 136 + c]), vl + g); \
    } \
    if (tid < 16) cpa4(smem_u32(&st[s].mk[tid * 4]), mrow + (kt) * 64 + tid * 4); \
    CP_COMMIT(); } while (0)

    F_LOAD(0, 0);
    F_LOAD(1, 1);

    const int cb = (lane & 3) * 2;

    for (int kt = 0; kt < 32; kt++) {
        if (kt < 31) CP_WAIT1(); else CP_WAIT0();
        __syncthreads();
        FStage* cs = &st[kt & 1];

        // ---- S = Q K^T (already in log2 domain) ----
        float sc[8][4];
#pragma unroll
        for (int j = 0; j < 8; j++)
#pragma unroll
            for (int e = 0; e < 4; e++) sc[j][e] = 0.0f;

#pragma unroll
        for (int ks = 0; ks < 8; ks++) {
#pragma unroll
            for (int jp = 0; jp < 4; jp++) {
                int krow = jp * 16 + lr + (lg >> 1) * 8;
                int kcol = ks * 16 + (lg & 1) * 8;
                uint32_t bh_[4], bl_[4];
                ldm_x4(bh_, smem_u32(&cs->kh[krow * 136 + kcol]));
                ldm_x4(bl_, smem_u32(&cs->kl[krow * 136 + kcol]));
                mma_bf16(sc[2 * jp], qfh[ks], bh_);
                mma_bf16(sc[2 * jp], qfh[ks], bl_);
                mma_bf16(sc[2 * jp], qfl[ks], bh_);
                mma_bf16(sc[2 * jp + 1], qfh[ks], bh_ + 2);
                mma_bf16(sc[2 * jp + 1], qfh[ks], bl_ + 2);
                mma_bf16(sc[2 * jp + 1], qfl[ks], bh_ + 2);
            }
        }

        // ---- mask ----
#pragma unroll
        for (int j = 0; j < 8; j++) {
            bool mk0 = cs->mk[j * 8 + cb] != 0;
            bool mk1 = cs->mk[j * 8 + cb + 1] != 0;
            if (mk0) { sc[j][0] = -1e30f; sc[j][2] = -1e30f; }
            if (mk1) { sc[j][1] = -1e30f; sc[j][3] = -1e30f; }
        }

        // ---- online softmax (log2 domain) ----
#pragma unroll
        for (int rr = 0; rr < 2; rr++) {
            float mx = -3.4e38f;
#pragma unroll
            for (int j = 0; j < 8; j++)
                mx = fmaxf(mx, fmaxf(sc[j][2 * rr], sc[j][2 * rr + 1]));
            mx = fmaxf(mx, __shfl_xor_sync(0xffffffffu, mx, 1));
            mx = fmaxf(mx, __shfl_xor_sync(0xffffffffu, mx, 2));
            float mnew = fmaxf(m_i[rr], mx);
            float alpha = exp2f(m_i[rr] - mnew);
            m_i[rr] = mnew;
            float s = 0.0f;
#pragma unroll
            for (int j = 0; j < 8; j++) {
                float p0 = exp2f(sc[j][2 * rr] - mnew);
                float p1 = exp2f(sc[j][2 * rr + 1] - mnew);
                sc[j][2 * rr] = p0;
                sc[j][2 * rr + 1] = p1;
                s += p0 + p1;
            }
            s += __shfl_xor_sync(0xffffffffu, s, 1);
            s += __shfl_xor_sync(0xffffffffu, s, 2);
            l_i[rr] = l_i[rr] * alpha + s;
#pragma unroll
            for (int j = 0; j < 16; j++) {
                oc[j][2 * rr] *= alpha;
                oc[j][2 * rr + 1] *= alpha;
            }
        }

        // ---- O += P V ----
#pragma unroll
        for (int ks = 0; ks < 4; ks++) {
            uint32_t ph[4], pl[4];
            split_pack(sc[2 * ks][0], sc[2 * ks][1], ph[0], pl[0]);
            split_pack(sc[2 * ks][2], sc[2 * ks][3], ph[1], pl[1]);
            split_pack(sc[2 * ks + 1][0], sc[2 * ks + 1][1], ph[2], pl[2]);
            split_pack(sc[2 * ks + 1][2], sc[2 * ks + 1][3], ph[3], pl[3]);
#pragma unroll
            for (int jp = 0; jp < 8; jp++) {
                int vrow = ks * 16 + lr + (lg & 1) * 8;
                int vcol = jp * 16 + (lg >> 1) * 8;
                uint32_t vh_[4], vl_[4];
                ldm_x4_t(vh_, smem_u32(&cs->vh[vrow * 136 + vcol]));
                ldm_x4_t(vl_, smem_u32(&cs->vl[vrow * 136 + vcol]));
                mma_bf16(oc[2 * jp], ph, vh_);
                mma_bf16(oc[2 * jp], ph, vl_);
                mma_bf16(oc[2 * jp], pl, vh_);
                mma_bf16(oc[2 * jp + 1], ph, vh_ + 2);
                mma_bf16(oc[2 * jp + 1], ph, vl_ + 2);
                mma_bf16(oc[2 * jp + 1], pl, vh_ + 2);
            }
        }
        __syncthreads();
        if (kt + 2 < 32) F_LOAD(kt & 1, kt + 2);
    }
#undef F_LOAD

    // ---- epilogue: normalize + split-store y [B,TQ,H*D] ----
    float inv0 = 1.0f / l_i[0];
    float inv1 = 1.0f / l_i[1];
    int q0 = qt * 128 + w * 16 + (lane >> 2);
    int q1 = q0 + 8;
    size_t base0 = ((size_t)b * TQ + q0) * HD + h * DD;
    size_t base1 = ((size_t)b * TQ + q1) * HD + h * DD;
#pragma unroll
    for (int j = 0; j < 16; j++) {
        int d = j * 8 + cb;
        bf16 h0, l0, h1, l1;
        split2(oc[j][0] * inv0, h0, l0); split2(oc[j][1] * inv0, h1, l1);
        *(__nv_bfloat162*)(yh + base0 + d) = __halves2bfloat162(h0, h1);
        *(__nv_bfloat162*)(yl + base0 + d) = __halves2bfloat162(l0, l1);
        split2(oc[j][2] * inv1, h0, l0); split2(oc[j][3] * inv1, h1, l1);
        *(__nv_bfloat162*)(yh + base1 + d) = __halves2bfloat162(h0, h1);
        *(__nv_bfloat162*)(yl + base1 + d) = __halves2bfloat162(l0, l1);
    }
}

// ---------------------------------------------------------------------------
extern "C" void kernel_launch(void* const* d_in, const int* in_sizes, int n_in,
                              void* d_out, int out_size) {
    const float* x     = (const float*)d_in[0];
    const float* xall  = (const float*)d_in[1];
    const int*   posx  = (const int*)d_in[2];
    const int*   posxa = (const int*)d_in[3];
    const void*  mask  = d_in[4];
    const float* Wq = (const float*)d_in[5];
    const float* Wk = (const float*)d_in[6];
    const float* Wv = (const float*)d_in[7];
    const float* Wo = (const float*)d_in[8];
    float* out = (float*)d_out;

    float *qptr, *kptr;
    cudaGetSymbolAddress((void**)&qptr, g_q);
    cudaGetSymbolAddress((void**)&kptr, g_k);
    bf16 *xh, *xl, *ah, *al, *qhp, *qlp, *khp, *klp, *vhp, *vlp, *yhp, *ylp;
    bf16 *wqh, *wql, *wkh, *wkl, *wvh, *wvl, *woh, *wol;
    cudaGetSymbolAddress((void**)&xh, g_xh);   cudaGetSymbolAddress((void**)&xl, g_xl);
    cudaGetSymbolAddress((void**)&ah, g_ah);   cudaGetSymbolAddress((void**)&al, g_al);
    cudaGetSymbolAddress((void**)&qhp, g_qh);  cudaGetSymbolAddress((void**)&qlp, g_ql);
    cudaGetSymbolAddress((void**)&khp, g_kh);  cudaGetSymbolAddress((void**)&klp, g_kl);
    cudaGetSymbolAddress((void**)&vhp, g_vh);  cudaGetSymbolAddress((void**)&vlp, g_vl);
    cudaGetSymbolAddress((void**)&yhp, g_yh);  cudaGetSymbolAddress((void**)&ylp, g_yl);
    cudaGetSymbolAddress((void**)&wqh, g_wqh); cudaGetSymbolAddress((void**)&wql, g_wql);
    cudaGetSymbolAddress((void**)&wkh, g_wkh); cudaGetSymbolAddress((void**)&wkl, g_wkl);
    cudaGetSymbolAddress((void**)&wvh, g_wvh); cudaGetSymbolAddress((void**)&wvl, g_wvl);
    cudaGetSymbolAddress((void**)&woh, g_woh); cudaGetSymbolAddress((void**)&wol, g_wol);

    const int smem_gemm = (int)(2 * sizeof(GStage));     // 75776
    cudaFuncSetAttribute(hmma_gemm<0>, cudaFuncAttributeMaxDynamicSharedMemorySize, smem_gemm);
    cudaFuncSetAttribute(hmma_gemm<1>, cudaFuncAttributeMaxDynamicSharedMemorySize, smem_gemm);
    cudaFuncSetAttribute(hmma_gemm<2>, cudaFuncAttributeMaxDynamicSharedMemorySize, smem_gemm);
    const int smem_flash = (int)(2 * sizeof(FStage));    // 139392
    cudaFuncSetAttribute(flash_kernel, cudaFuncAttributeMaxDynamicSharedMemorySize, smem_flash);

    // 0. mask + tables
    mask_detect_kernel<<<1, 256>>>((const unsigned int*)mask);
    mask_convert_kernel<<<(BB * TT) / 256, 256>>>(mask);
    rope_tables_kernel<<<NBLOCK, DD>>>();

    // 1. pre-split inputs and weights
    split_convert_kernel<<<(MM * KK) / 1024, 256>>>(x, xh, xl);
    split_convert_kernel<<<(MM * KK) / 1024, 256>>>(xall, ah, al);
    split_convert_kernel<<<(KK * NN) / 1024, 256>>>(Wq, wqh, wql);
    split_convert_kernel<<<(KK * NN) / 1024, 256>>>(Wk, wkh, wkl);
    split_convert_kernel<<<(KK * NN) / 1024, 256>>>(Wv, wvh, wvl);
    split_convert_kernel<<<(KK * NN) / 1024, 256>>>(Wo, woh, wol);

    // 2. projections
    dim3 ggrid(NN / 128, MM / 128);
    hmma_gemm<1><<<ggrid, 256, smem_gemm>>>(xh, xl, wqh, wql, qptr, nullptr, nullptr);
    hmma_gemm<1><<<ggrid, 256, smem_gemm>>>(ah, al, wkh, wkl, kptr, nullptr, nullptr);
    hmma_gemm<2><<<ggrid, 256, smem_gemm>>>(ah, al, wvh, wvl, nullptr, vhp, vlp);

    // 3. RoPE + split (q gets softmax scale*log2e folded in)
    const float qfac = 0.08838834764831845f * 1.4426950408889634f;
    rope_split_kernel<<<BB * HH * TQ, DD>>>(qptr, posx, qhp, qlp, qfac);
    rope_split_kernel<<<BB * HH * TT, DD>>>(kptr, posxa, khp, klp, 1.0f);

    // 4. flash attention -> split y
    dim3 fgrid(TQ / 128, BB * HH);
    flash_kernel<<<fgrid, 256, smem_flash>>>(qhp, qlp, khp, klp, vhp, vlp, yhp, ylp);

    // 5. output projection
    hmma_gemm<0><<<ggrid, 256, smem_gemm>>>(yhp, ylp, woh, wol, out, nullptr, nullptr);
}